// round 5
// baseline (speedup 1.0000x reference)
#include <cuda_runtime.h>
#include <cuda_bf16.h>
#include <math.h>

// ---------------------------------------------------------------------------
// SpatialTransformerInputHead  (B=128, H=W=256, C=1)
//   conv1 5x5 1->14 + relu + maxpool2  (fp32 f32x2)     -> g_buf1 fp32 NHWC16
//   conv2 5x5 14->32 + relu + maxpool2 (tf32 mma.sync)  -> g_buf2 fp32 NHWC
//   dense 119072->120 relu, 120->84 relu, 84->6 -> theta
//   bilinear grid sample + 1x1 conv + sigmoid -> [128,256,256,1]
// ---------------------------------------------------------------------------

typedef unsigned long long ull;
typedef unsigned int uint32;

#define BATCH 128
#define HW    256
#define P1    126
#define P2    61
#define FLAT  (61*61*32)   // 119072
#define KSPLITS 64
#define KCHUNK  1861

// --------- scratch -----------------------------------------------------------
__device__ float g_buf1[(size_t)BATCH*P1*P1*16];   // conv1 pooled, NHWC ch-pad 16, fp32
__device__ float g_buf2[(size_t)BATCH*FLAT];       // conv2 pooled, NHWC flat, fp32
__device__ float g_part[(size_t)KSPLITS*BATCH*120];
__device__ float g_theta[BATCH*6];

// --------- helpers -----------------------------------------------------------
__device__ __forceinline__ ull pk2(float v) {
    ull r;
    asm("mov.b64 %0, {%1, %2};" : "=l"(r) : "f"(v), "f"(v));
    return r;
}
__device__ __forceinline__ void upk2(ull v, float& lo, float& hi) {
    asm("mov.b64 {%0, %1}, %2;" : "=f"(lo), "=f"(hi) : "l"(v));
}
#define FMA2(d, a, b) asm("fma.rn.f32x2 %0, %1, %2, %0;" : "+l"(d) : "l"(a), "l"(b))

__device__ __forceinline__ float tf32r(float v) {
    float o;
    asm("cvt.rna.tf32.f32 %0, %1;" : "=f"(o) : "f"(v));
    return o;
}

#define MMA_TF32(c, a0, a1, a2, a3, b0, b1)                                    \
    asm volatile(                                                              \
        "mma.sync.aligned.m16n8k8.row.col.f32.tf32.tf32.f32 "                  \
        "{%0,%1,%2,%3}, {%4,%5,%6,%7}, {%8,%9}, {%0,%1,%2,%3};"                \
        : "+f"((c)[0]), "+f"((c)[1]), "+f"((c)[2]), "+f"((c)[3])               \
        : "r"(a0), "r"(a1), "r"(a2), "r"(a3), "r"(b0), "r"(b1))

// ===========================================================================
// conv1 (5x5, 1->14) + relu + maxpool2, fp32 f32x2 math, fp32 NHWC16 output.
// grid (8,8,128), 256 threads.
// ===========================================================================
__global__ void __launch_bounds__(256) conv1_kernel(
    const float* __restrict__ x, const float* __restrict__ w,
    const float* __restrict__ bias)
{
    __shared__ __align__(16) float sw[352];
    __shared__ __align__(16) float sb[16];
    __shared__ __align__(16) float sin_[36*36];

    const int b  = blockIdx.z;
    const int ox = blockIdx.x * 32;
    const int oy = blockIdx.y * 32;
    const int tid = threadIdx.x;

    for (int i = tid; i < 350; i += 256) sw[i] = w[i];
    if (tid < 14)  sb[tid] = bias[tid];

    const float* xb = x + (size_t)b * (HW*HW);
    for (int i = tid; i < 36*36; i += 256) {
        int r = i / 36, c = i % 36;
        int gy = oy + r, gx = ox + c;
        sin_[i] = (gy < HW && gx < HW) ? xb[gy*HW + gx] : 0.f;
    }
    __syncthreads();

    const int tx = tid & 15, ty = tid >> 4;

    ull acc[4][7];
#pragma unroll
    for (int p = 0; p < 4; ++p)
#pragma unroll
        for (int j = 0; j < 7; ++j) acc[p][j] = 0ull;

    const float* ib = sin_ + (2*ty)*36 + 2*tx;
#pragma unroll
    for (int dy = 0; dy < 5; ++dy) {
        const float* ra = ib + dy*36;
        const float* rb = ra + 36;
#pragma unroll
        for (int dx = 0; dx < 5; ++dx) {
            ull p00 = pk2(ra[dx]);
            ull p01 = pk2(ra[dx+1]);
            ull p10 = pk2(rb[dx]);
            ull p11 = pk2(rb[dx+1]);
            const ull* wp = (const ull*)&sw[(dy*5 + dx)*14];
#pragma unroll
            for (int j = 0; j < 7; ++j) {
                ull wv = wp[j];
                FMA2(acc[0][j], p00, wv);
                FMA2(acc[1][j], p01, wv);
                FMA2(acc[2][j], p10, wv);
                FMA2(acc[3][j], p11, wv);
            }
        }
    }

    const int x0 = blockIdx.x*16 + tx;
    const int y0 = blockIdx.y*16 + ty;
    if (x0 < P1 && y0 < P1) {
        union { float4 f4[4]; float f[16]; } pk;
#pragma unroll
        for (int j = 0; j < 7; ++j) {
            float l0,h0,l1,h1,l2,h2,l3,h3;
            upk2(acc[0][j], l0, h0);
            upk2(acc[1][j], l1, h1);
            upk2(acc[2][j], l2, h2);
            upk2(acc[3][j], l3, h3);
            float m0 = fmaxf(fmaxf(l0,l1), fmaxf(l2,l3)) + sb[2*j];
            float m1 = fmaxf(fmaxf(h0,h1), fmaxf(h2,h3)) + sb[2*j+1];
            pk.f[2*j]   = fmaxf(m0, 0.f);
            pk.f[2*j+1] = fmaxf(m1, 0.f);
        }
        pk.f[14] = 0.f;
        pk.f[15] = 0.f;
        float4* dst = (float4*)(g_buf1 + ((size_t)(b*P1 + y0)*P1 + x0)*16);
        dst[0] = pk.f4[0]; dst[1] = pk.f4[1];
        dst[2] = pk.f4[2]; dst[3] = pk.f4[3];
    }
}

// ===========================================================================
// conv2 via tf32 mma.sync m16n8k8: 5x5 conv = 25 shifted 1x1 GEMMs, K=16 pad.
// Block: 16x16 pooled = 32x32 conv positions, 512 threads (16 warps),
// each warp: 2 conv rows x 32 cols (M=64) x N=32.
// A tile fp32 [36*36 pos][17 ch-pad], W fp32 [25][16][33 n-pad]; both
// pre-rounded with cvt.rna.tf32 so MMA truncation is exact.
// Epilogue: 2x2 maxpool + bias + relu -> fp32 NHWC flat g_buf2.
// ===========================================================================
#define C2_A_F   (1296*17)                 // 22032 floats
#define C2_W_F   (25*16*33)                // 13200 floats
#define C2_SMEM_B ((C2_A_F + C2_W_F + 32) * 4)   // ~141 KB

__global__ void __launch_bounds__(512) conv2_kernel(
    const float* __restrict__ w, const float* __restrict__ bias)
{
    extern __shared__ __align__(16) float smem[];
    float* At = smem;                  // [pos][17]
    float* Wt = smem + C2_A_F;         // [tap][16 k][33 n]
    float* sb = Wt + C2_W_F;           // [32]

    const int b   = blockIdx.z;
    const int px0 = blockIdx.x * 16;
    const int py0 = blockIdx.y * 16;
    const int ix0 = px0 * 2;
    const int iy0 = py0 * 2;
    const int tid = threadIdx.x;

    // weights: HWIO fp32 [tap][ci(14)][co(32)] -> tf32 [tap][k16][n33]
    for (int i = tid; i < C2_W_F; i += 512) {
        int tap = i / 528;
        int rem = i - tap*528;
        int k   = rem / 33;
        int n   = rem - k*33;
        float v = (k < 14 && n < 32) ? w[tap*448 + k*32 + n] : 0.f;
        Wt[i] = tf32r(v);
    }
    if (tid < 32) sb[tid] = bias[tid];

    // A tile: 36x36 positions x 16 ch fp32, tf32-rounded, ch-pad 17
    for (int p = tid; p < 1296; p += 512) {
        int r = p / 36, c = p % 36;
        int gy = iy0 + r, gx = ix0 + c;
        float* d = At + p*17;
        if (gy < P1 && gx < P1) {
            const float4* s = (const float4*)(g_buf1 + ((size_t)(b*P1 + gy)*P1 + gx)*16);
            float4 v0 = s[0], v1 = s[1], v2 = s[2], v3 = s[3];
            d[0]=tf32r(v0.x); d[1]=tf32r(v0.y); d[2]=tf32r(v0.z); d[3]=tf32r(v0.w);
            d[4]=tf32r(v1.x); d[5]=tf32r(v1.y); d[6]=tf32r(v1.z); d[7]=tf32r(v1.w);
            d[8]=tf32r(v2.x); d[9]=tf32r(v2.y); d[10]=tf32r(v2.z); d[11]=tf32r(v2.w);
            d[12]=tf32r(v3.x); d[13]=tf32r(v3.y); d[14]=0.f; d[15]=0.f;
        } else {
#pragma unroll
            for (int j = 0; j < 16; ++j) d[j] = 0.f;
        }
        d[16] = 0.f;
    }
    __syncthreads();

    const int warp = tid >> 5, lane = tid & 31;
    const int y0 = 2 * warp;           // conv rows y0, y0+1
    const int gr = lane >> 2;          // fragment row group (0..7)
    const int gc = lane & 3;           // fragment col group (0..3)

    float cacc[2][2][4][4];
#pragma unroll
    for (int s = 0; s < 2; ++s)
#pragma unroll
        for (int xh = 0; xh < 2; ++xh)
#pragma unroll
            for (int nf = 0; nf < 4; ++nf)
#pragma unroll
                for (int k = 0; k < 4; ++k) cacc[s][xh][nf][k] = 0.f;

#pragma unroll 1
    for (int tap = 0; tap < 25; ++tap) {
        const int dy = tap / 5, dx = tap % 5;

        // B fragments: b0 = W[k0+gc][n], b1 = W[k0+gc+4][n], n = nf*8 + gr
        uint32 bf[2][4][2];
        const float* wt = Wt + tap*528 + gr;
#pragma unroll
        for (int kc = 0; kc < 2; ++kc)
#pragma unroll
        for (int nf = 0; nf < 4; ++nf) {
            const float* wp = wt + (kc*8 + gc)*33 + nf*8;
            bf[kc][nf][0] = __float_as_uint(wp[0]);
            bf[kc][nf][1] = __float_as_uint(wp[4*33]);
        }

#pragma unroll
        for (int s = 0; s < 2; ++s) {
            const int rowbase = (y0 + s + dy)*36 + dx;
#pragma unroll
            for (int xh = 0; xh < 2; ++xh) {
                const float* a0p = At + (rowbase + xh*16 + gr)*17;
                const float* a1p = a0p + 8*17;
#pragma unroll
                for (int kc = 0; kc < 2; ++kc) {
                    uint32 a0 = __float_as_uint(a0p[kc*8 + gc]);
                    uint32 a1 = __float_as_uint(a1p[kc*8 + gc]);
                    uint32 a2 = __float_as_uint(a0p[kc*8 + gc + 4]);
                    uint32 a3 = __float_as_uint(a1p[kc*8 + gc + 4]);
#pragma unroll
                    for (int nf = 0; nf < 4; ++nf)
                        MMA_TF32(cacc[s][xh][nf], a0, a1, a2, a3,
                                 bf[kc][nf][0], bf[kc][nf][1]);
                }
            }
        }
    }

    // epilogue: 2x2 maxpool + bias + relu -> fp32 NHWC
    const int py = py0 + warp;
    const int r  = lane >> 2;
    const bool active = ((r & 1) == 0);
    const int j = r >> 1;
    const int n0 = (lane & 3) * 2;

#pragma unroll
    for (int xh = 0; xh < 2; ++xh)
#pragma unroll
    for (int nf = 0; nf < 4; ++nf) {
        float m0 = fmaxf(cacc[0][xh][nf][0], cacc[1][xh][nf][0]);
        float m1 = fmaxf(cacc[0][xh][nf][1], cacc[1][xh][nf][1]);
        float m2 = fmaxf(cacc[0][xh][nf][2], cacc[1][xh][nf][2]);
        float m3 = fmaxf(cacc[0][xh][nf][3], cacc[1][xh][nf][3]);
        float o0 = fmaxf(m0, __shfl_down_sync(0xffffffffu, m0, 4));
        float o1 = fmaxf(m1, __shfl_down_sync(0xffffffffu, m1, 4));
        float o2 = fmaxf(m2, __shfl_down_sync(0xffffffffu, m2, 4));
        float o3 = fmaxf(m3, __shfl_down_sync(0xffffffffu, m3, 4));
        if (active && py < P2) {
            const int ch  = nf*8 + n0;
            const float b0v = sb[ch], b1v = sb[ch+1];
            const int pxa = px0 + xh*8 + j;
            const int pxb = pxa + 4;
            if (pxa < P2) {
                float2 v = make_float2(fmaxf(o0 + b0v, 0.f), fmaxf(o1 + b1v, 0.f));
                *(float2*)(g_buf2 + (((size_t)b*P2 + py)*P2 + pxa)*32 + ch) = v;
            }
            if (pxb < P2) {
                float2 v = make_float2(fmaxf(o2 + b0v, 0.f), fmaxf(o3 + b1v, 0.f));
                *(float2*)(g_buf2 + (((size_t)b*P2 + py)*P2 + pxb)*32 + ch) = v;
            }
        }
    }
}

// ===========================================================================
// dense1 split-K GEMM:  [128 x 119072] @ [119072 x 120] -> partials.
// grid (5, 64); f32x2-packed inner loop; fp32 activations.
// ===========================================================================
__global__ void __launch_bounds__(256) dense1_kernel(const float* __restrict__ w)
{
    __shared__ __align__(16) float As[32*129];
    __shared__ __align__(16) float Ws[32*24];

    const int o0   = blockIdx.x * 24;
    const int k0   = blockIdx.y * KCHUNK;
    const int kend = min(k0 + KCHUNK, FLAT);
    const int tid  = threadIdx.x;
    const int bb   = tid & 127;
    const int g    = tid >> 7;

    ull acc[6];
#pragma unroll
    for (int j = 0; j < 6; ++j) acc[j] = 0ull;

    for (int kb = k0; kb < kend; kb += 32) {
        for (int i = tid; i < 128*32; i += 256) {
            int r  = i >> 5;
            int kk = i & 31;
            int k  = kb + kk;
            As[kk*129 + r] = (k < kend) ? g_buf2[(size_t)r*FLAT + k] : 0.f;
        }
        for (int i = tid; i < 32*24; i += 256) {
            int kk = i / 24, oo = i - kk*24;
            int k = kb + kk;
            Ws[i] = (k < kend) ? w[(size_t)k*120 + o0 + oo] : 0.f;
        }
        __syncthreads();
#pragma unroll
        for (int kk = 0; kk < 32; ++kk) {
            ull a2 = pk2(As[kk*129 + bb]);
            const ull* wsp = (const ull*)&Ws[kk*24 + g*12];
#pragma unroll
            for (int j = 0; j < 6; ++j)
                FMA2(acc[j], a2, wsp[j]);
        }
        __syncthreads();
    }

    float* p = g_part + ((size_t)blockIdx.y*BATCH + bb)*120 + o0 + g*12;
#pragma unroll
    for (int j = 0; j < 6; ++j) {
        float lo, hi;
        upk2(acc[j], lo, hi);
        p[2*j]   = lo;
        p[2*j+1] = hi;
    }
}

// ===========================================================================
// dense23: reduce split-K partials (4-way ILP) + bias + relu -> h1;
//          h2 = relu(h1 @ d2_w + b2);  theta = h2 @ d3_w + b3.
// ===========================================================================
__global__ void __launch_bounds__(128) dense23_kernel(
    const float* __restrict__ d1b,
    const float* __restrict__ d2w, const float* __restrict__ d2b,
    const float* __restrict__ d3w, const float* __restrict__ d3b)
{
    __shared__ float h1[120];
    __shared__ float h2[84];
    const int b = blockIdx.x, t = threadIdx.x;

    if (t < 120) {
        const float* gp = g_part + (size_t)b*120 + t;
        float s0 = d1b[t], s1 = 0.f, s2 = 0.f, s3 = 0.f;
#pragma unroll 4
        for (int i = 0; i < KSPLITS; i += 4) {
            s0 += gp[(size_t)(i+0)*BATCH*120];
            s1 += gp[(size_t)(i+1)*BATCH*120];
            s2 += gp[(size_t)(i+2)*BATCH*120];
            s3 += gp[(size_t)(i+3)*BATCH*120];
        }
        h1[t] = fmaxf((s0 + s1) + (s2 + s3), 0.f);
    }
    __syncthreads();
    if (t < 84) {
        float s = d2b[t];
#pragma unroll 4
        for (int k = 0; k < 120; ++k)
            s = fmaf(h1[k], d2w[k*84 + t], s);
        h2[t] = fmaxf(s, 0.f);
    }
    __syncthreads();
    if (t < 6) {
        float s = d3b[t];
#pragma unroll 4
        for (int k = 0; k < 84; ++k)
            s = fmaf(h2[k], d3w[k*6 + t], s);
        g_theta[b*6 + t] = s;
    }
}

// ===========================================================================
// sampler: affine grid + bilinear sample + 1x1 conv + sigmoid.
// ===========================================================================
__global__ void __launch_bounds__(256) sampler_kernel(
    const float* __restrict__ x, const float* __restrict__ ow,
    const float* __restrict__ ob, float* __restrict__ out)
{
    __shared__ float th[6];
    const int b = blockIdx.y;
    const int h = blockIdx.x;
    const int w = threadIdx.x;
    if (w < 6) th[w] = g_theta[b*6 + w];
    __syncthreads();

    const float gx = (float)w * (2.f/256.f) - 1.f;
    const float gy = (float)h * (2.f/256.f) - 1.f;
    const float px = (th[0]*gx + th[1]*gy + th[2] + 1.f) * 128.f;
    const float py = (th[3]*gx + th[4]*gy + th[5] + 1.f) * 128.f;

    const int fx = (int)floorf(px);
    const int fy = (int)floorf(py);
    const int x1 = min(max(fx,     0), HW-1);
    const int x2 = min(max(fx + 1, 0), HW-1);
    const int y1 = min(max(fy,     0), HW-1);
    const int y2 = min(max(fy + 1, 0), HW-1);

    const float* img = x + (size_t)b * (HW*HW);
    const float p11 = img[y1*HW + x1];
    const float p12 = img[y2*HW + x1];
    const float p21 = img[y1*HW + x2];
    const float p22 = img[y2*HW + x2];

    const float wx1 = (float)x2 - px;
    const float wx2 = px - (float)x1;
    const float wy1 = (float)y2 - py;
    const float wy2 = py - (float)y1;

    const float r = wx1*(wy1*p11 + wy2*p12) + wx2*(wy1*p21 + wy2*p22);
    const float t = r * __ldg(ow) + __ldg(ob);
    out[((size_t)b*HW + h)*HW + w] = 1.f / (1.f + expf(-t));
}

// ===========================================================================
// launch
// ===========================================================================
extern "C" void kernel_launch(void* const* d_in, const int* in_sizes, int n_in,
                              void* d_out, int out_size)
{
    const float* x      = (const float*)d_in[0];
    const float* c1w    = (const float*)d_in[1];
    const float* c1b    = (const float*)d_in[2];
    const float* c2w    = (const float*)d_in[3];
    const float* c2b    = (const float*)d_in[4];
    const float* d1w    = (const float*)d_in[5];
    const float* d1b    = (const float*)d_in[6];
    const float* d2w    = (const float*)d_in[7];
    const float* d2b    = (const float*)d_in[8];
    const float* d3w    = (const float*)d_in[9];
    const float* d3b    = (const float*)d_in[10];
    const float* outw   = (const float*)d_in[11];
    const float* outb   = (const float*)d_in[12];
    float* out = (float*)d_out;

    (void)in_sizes; (void)n_in; (void)out_size;

    cudaFuncSetAttribute(conv2_kernel,
                         cudaFuncAttributeMaxDynamicSharedMemorySize, C2_SMEM_B);

    conv1_kernel<<<dim3(8, 8, BATCH), 256>>>(x, c1w, c1b);
    conv2_kernel<<<dim3(4, 4, BATCH), 512, C2_SMEM_B>>>(c2w, c2b);
    dense1_kernel<<<dim3(5, KSPLITS), 256>>>(d1w);
    dense23_kernel<<<BATCH, 128>>>(d1b, d2w, d2b, d3w, d3b);
    sampler_kernel<<<dim3(HW, BATCH), 256>>>(x, outw, outb, out);
}

// round 6
// speedup vs baseline: 1.3146x; 1.3146x over previous
#include <cuda_runtime.h>
#include <cuda_bf16.h>
#include <math.h>

// ---------------------------------------------------------------------------
// SpatialTransformerInputHead  (B=128, H=W=256, C=1)
//   conv1 5x5 1->14 + relu + maxpool2  (fp32 f32x2)        -> g_buf1 fp32 NHWC16
//   conv2 5x5 14->32 + relu + maxpool2 (tf32 mma + ldmatrix)-> g_buf2 fp32 NHWC
//   dense 119072->120 relu, 120->84 relu, 84->6 -> theta
//   bilinear grid sample + 1x1 conv + sigmoid -> [128,256,256,1]
// ---------------------------------------------------------------------------

typedef unsigned long long ull;
typedef unsigned int uint32;

#define BATCH 128
#define HW    256
#define P1    126
#define P2    61
#define FLAT  (61*61*32)   // 119072
#define KSPLITS 128
#define KCHUNK  931        // ceil(119072/128)

// --------- scratch -----------------------------------------------------------
__device__ float g_buf1[(size_t)BATCH*P1*P1*16];   // conv1 pooled, NHWC16, fp32
__device__ float g_buf2[(size_t)BATCH*FLAT];       // conv2 pooled, NHWC flat, fp32
__device__ float g_part[(size_t)KSPLITS*BATCH*120];
__device__ float g_theta[BATCH*6];

// --------- helpers -----------------------------------------------------------
__device__ __forceinline__ ull pk2(float v) {
    ull r;
    asm("mov.b64 %0, {%1, %2};" : "=l"(r) : "f"(v), "f"(v));
    return r;
}
__device__ __forceinline__ void upk2(ull v, float& lo, float& hi) {
    asm("mov.b64 {%0, %1}, %2;" : "=f"(lo), "=f"(hi) : "l"(v));
}
#define FMA2(d, a, b) asm("fma.rn.f32x2 %0, %1, %2, %0;" : "+l"(d) : "l"(a), "l"(b))

__device__ __forceinline__ float tf32r(float v) {
    float o;
    asm("cvt.rna.tf32.f32 %0, %1;" : "=f"(o) : "f"(v));
    return o;
}
__device__ __forceinline__ uint32 smem_u32(const void* p) {
    uint32 a;
    asm("{ .reg .u64 t; cvta.to.shared.u64 t, %1; cvt.u32.u64 %0, t; }"
        : "=r"(a) : "l"(p));
    return a;
}

#define MMA_TF32(c, a0, a1, a2, a3, b0, b1)                                    \
    asm volatile(                                                              \
        "mma.sync.aligned.m16n8k8.row.col.f32.tf32.tf32.f32 "                  \
        "{%0,%1,%2,%3}, {%4,%5,%6,%7}, {%8,%9}, {%0,%1,%2,%3};"                \
        : "+f"((c)[0]), "+f"((c)[1]), "+f"((c)[2]), "+f"((c)[3])               \
        : "r"(a0), "r"(a1), "r"(a2), "r"(a3), "r"(b0), "r"(b1))

#define LDSM_X4(r0, r1, r2, r3, addr)                                          \
    asm volatile("ldmatrix.sync.aligned.m8n8.x4.shared.b16 {%0,%1,%2,%3}, [%4];" \
        : "=r"(r0), "=r"(r1), "=r"(r2), "=r"(r3) : "r"(addr))

// ===========================================================================
// conv1 (5x5, 1->14) + relu + maxpool2, fp32 f32x2 math, fp32 NHWC16 output.
// grid (8,8,128), 256 threads.
// ===========================================================================
__global__ void __launch_bounds__(256) conv1_kernel(
    const float* __restrict__ x, const float* __restrict__ w,
    const float* __restrict__ bias)
{
    __shared__ __align__(16) float sw[352];
    __shared__ __align__(16) float sb[16];
    __shared__ __align__(16) float sin_[36*36];

    const int b  = blockIdx.z;
    const int ox = blockIdx.x * 32;
    const int oy = blockIdx.y * 32;
    const int tid = threadIdx.x;

    for (int i = tid; i < 350; i += 256) sw[i] = w[i];
    if (tid < 14)  sb[tid] = bias[tid];

    const float* xb = x + (size_t)b * (HW*HW);
    for (int i = tid; i < 36*36; i += 256) {
        int r = i / 36, c = i % 36;
        int gy = oy + r, gx = ox + c;
        sin_[i] = (gy < HW && gx < HW) ? xb[gy*HW + gx] : 0.f;
    }
    __syncthreads();

    const int tx = tid & 15, ty = tid >> 4;

    ull acc[4][7];
#pragma unroll
    for (int p = 0; p < 4; ++p)
#pragma unroll
        for (int j = 0; j < 7; ++j) acc[p][j] = 0ull;

    const float* ib = sin_ + (2*ty)*36 + 2*tx;
#pragma unroll
    for (int dy = 0; dy < 5; ++dy) {
        const float* ra = ib + dy*36;
        const float* rb = ra + 36;
#pragma unroll
        for (int dx = 0; dx < 5; ++dx) {
            ull p00 = pk2(ra[dx]);
            ull p01 = pk2(ra[dx+1]);
            ull p10 = pk2(rb[dx]);
            ull p11 = pk2(rb[dx+1]);
            const ull* wp = (const ull*)&sw[(dy*5 + dx)*14];
#pragma unroll
            for (int j = 0; j < 7; ++j) {
                ull wv = wp[j];
                FMA2(acc[0][j], p00, wv);
                FMA2(acc[1][j], p01, wv);
                FMA2(acc[2][j], p10, wv);
                FMA2(acc[3][j], p11, wv);
            }
        }
    }

    const int x0 = blockIdx.x*16 + tx;
    const int y0 = blockIdx.y*16 + ty;
    if (x0 < P1 && y0 < P1) {
        union { float4 f4[4]; float f[16]; } pk;
#pragma unroll
        for (int j = 0; j < 7; ++j) {
            float l0,h0,l1,h1,l2,h2,l3,h3;
            upk2(acc[0][j], l0, h0);
            upk2(acc[1][j], l1, h1);
            upk2(acc[2][j], l2, h2);
            upk2(acc[3][j], l3, h3);
            float m0 = fmaxf(fmaxf(l0,l1), fmaxf(l2,l3)) + sb[2*j];
            float m1 = fmaxf(fmaxf(h0,h1), fmaxf(h2,h3)) + sb[2*j+1];
            pk.f[2*j]   = fmaxf(m0, 0.f);
            pk.f[2*j+1] = fmaxf(m1, 0.f);
        }
        pk.f[14] = 0.f;
        pk.f[15] = 0.f;
        float4* dst = (float4*)(g_buf1 + ((size_t)(b*P1 + y0)*P1 + x0)*16);
        dst[0] = pk.f4[0]; dst[1] = pk.f4[1];
        dst[2] = pk.f4[2]; dst[3] = pk.f4[3];
    }
}

// ===========================================================================
// conv2 via tf32 mma.sync m16n8k8 with ldmatrix-fed fragments.
// Block: 16x16 pooled = 32x32 conv positions, 512 threads (16 warps),
// each warp: 2 conv rows x 32 cols (M=64) x N=32.
// A tile: [36*36 pos][20 pad] fp32 tf32-rounded (80B row stride = conflict-free
// LDSM). W: [25 tap][32 n][20 pad k] fp32 tf32-rounded (transposed for B-LDSM).
// Epilogue: 2x2 maxpool + bias + relu -> fp32 NHWC flat g_buf2.
// ===========================================================================
#define C2_AT_F  (1296*20)                 // 25920 floats
#define C2_WT_F  (25*32*20)                // 16000 floats
#define C2_SMEM_B ((C2_AT_F + C2_WT_F + 32) * 4)   // 167808 B

__global__ void __launch_bounds__(512) conv2_kernel(
    const float* __restrict__ w, const float* __restrict__ bias)
{
    extern __shared__ __align__(16) float smem[];
    float* At = smem;                  // [pos][20]
    float* Wt = smem + C2_AT_F;        // [tap][n32][k20]
    float* sb = Wt + C2_WT_F;          // [32]

    const int b   = blockIdx.z;
    const int px0 = blockIdx.x * 16;
    const int py0 = blockIdx.y * 16;
    const int ix0 = px0 * 2;
    const int iy0 = py0 * 2;
    const int tid = threadIdx.x;

    // weights: HWIO fp32 [tap][ci(14)][co(32)] -> tf32 Wt[tap][n=co][k=ci pad20]
    for (int i = tid; i < C2_WT_F; i += 512) {
        int tap = i / 640;
        int rem = i - tap*640;
        int n   = rem / 20;
        int k   = rem - n*20;
        float v = (k < 14) ? w[tap*448 + k*32 + n] : 0.f;
        Wt[i] = tf32r(v);
    }
    if (tid < 32) sb[tid] = bias[tid];

    // A tile: 36x36 positions x 16 ch fp32 tf32-rounded, pad to 20
    for (int p = tid; p < 1296; p += 512) {
        int r = p / 36, c = p % 36;
        int gy = iy0 + r, gx = ix0 + c;
        float* d = At + p*20;
        if (gy < P1 && gx < P1) {
            const float4* s4 = (const float4*)(g_buf1 + ((size_t)(b*P1 + gy)*P1 + gx)*16);
            float4 v0 = s4[0], v1 = s4[1], v2 = s4[2], v3 = s4[3];
            d[0]=tf32r(v0.x); d[1]=tf32r(v0.y); d[2]=tf32r(v0.z); d[3]=tf32r(v0.w);
            d[4]=tf32r(v1.x); d[5]=tf32r(v1.y); d[6]=tf32r(v1.z); d[7]=tf32r(v1.w);
            d[8]=tf32r(v2.x); d[9]=tf32r(v2.y); d[10]=tf32r(v2.z); d[11]=tf32r(v2.w);
            d[12]=tf32r(v3.x); d[13]=tf32r(v3.y); d[14]=0.f; d[15]=0.f;
        } else {
#pragma unroll
            for (int j = 0; j < 16; ++j) d[j] = 0.f;
        }
        d[16] = 0.f; d[17] = 0.f; d[18] = 0.f; d[19] = 0.f;
    }
    __syncthreads();

    const int warp = tid >> 5, lane = tid & 31;
    const int y0 = 2 * warp;           // conv rows y0, y0+1
    const uint32 atb = smem_u32(At);
    const uint32 wtb = smem_u32(Wt);

    // per-lane LDSM offsets (16x8-tf32 A tile; rows = x positions, 80B stride)
    const uint32 aoff = (uint32)((lane & 15)*80 + ((lane >> 4) & 1)*16);
    // B tile rows = n (80B stride): m0 rows0-7/k0-3, m1 rows0-7/k4-7,
    //                               m2 rows8-15/k0-3, m3 rows8-15/k4-7
    const uint32 boff = (uint32)(((lane & 7) + ((lane >> 4) & 1)*8)*80
                                 + ((lane >> 3) & 1)*16);

    float cacc[2][2][4][4];
#pragma unroll
    for (int s = 0; s < 2; ++s)
#pragma unroll
        for (int xh = 0; xh < 2; ++xh)
#pragma unroll
            for (int nf = 0; nf < 4; ++nf)
#pragma unroll
                for (int k = 0; k < 4; ++k) cacc[s][xh][nf][k] = 0.f;

#pragma unroll 1
    for (int tap = 0; tap < 25; ++tap) {
        const int dy = tap / 5, dx = tap - 5*dy;

        // B fragments: br[kc][np] = {b0(nf=2np), b1(nf=2np), b0(nf=2np+1), b1(nf=2np+1)}
        uint32 br[2][2][4];
        const uint32 wbase = wtb + (uint32)(tap*2560) + boff;
#pragma unroll
        for (int kc = 0; kc < 2; ++kc)
#pragma unroll
        for (int np = 0; np < 2; ++np)
            LDSM_X4(br[kc][np][0], br[kc][np][1], br[kc][np][2], br[kc][np][3],
                    wbase + (uint32)(np*1280 + kc*32));

#pragma unroll
        for (int s = 0; s < 2; ++s) {
            const int row = y0 + s + dy;
#pragma unroll
            for (int xh = 0; xh < 2; ++xh) {
                const uint32 abase = atb + (uint32)((row*36 + dx + xh*16)*80) + aoff;
#pragma unroll
                for (int kc = 0; kc < 2; ++kc) {
                    uint32 a0, a1, a2, a3;
                    LDSM_X4(a0, a1, a2, a3, abase + (uint32)(kc*32));
                    MMA_TF32(cacc[s][xh][0], a0, a1, a2, a3, br[kc][0][0], br[kc][0][1]);
                    MMA_TF32(cacc[s][xh][1], a0, a1, a2, a3, br[kc][0][2], br[kc][0][3]);
                    MMA_TF32(cacc[s][xh][2], a0, a1, a2, a3, br[kc][1][0], br[kc][1][1]);
                    MMA_TF32(cacc[s][xh][3], a0, a1, a2, a3, br[kc][1][2], br[kc][1][3]);
                }
            }
        }
    }

    // epilogue: 2x2 maxpool + bias + relu -> fp32 NHWC
    const int py = py0 + warp;
    const int r  = lane >> 2;
    const bool active = ((r & 1) == 0);
    const int j = r >> 1;
    const int n0 = (lane & 3) * 2;

#pragma unroll
    for (int xh = 0; xh < 2; ++xh)
#pragma unroll
    for (int nf = 0; nf < 4; ++nf) {
        float m0 = fmaxf(cacc[0][xh][nf][0], cacc[1][xh][nf][0]);
        float m1 = fmaxf(cacc[0][xh][nf][1], cacc[1][xh][nf][1]);
        float m2 = fmaxf(cacc[0][xh][nf][2], cacc[1][xh][nf][2]);
        float m3 = fmaxf(cacc[0][xh][nf][3], cacc[1][xh][nf][3]);
        float o0 = fmaxf(m0, __shfl_down_sync(0xffffffffu, m0, 4));
        float o1 = fmaxf(m1, __shfl_down_sync(0xffffffffu, m1, 4));
        float o2 = fmaxf(m2, __shfl_down_sync(0xffffffffu, m2, 4));
        float o3 = fmaxf(m3, __shfl_down_sync(0xffffffffu, m3, 4));
        if (active && py < P2) {
            const int ch  = nf*8 + n0;
            const float b0v = sb[ch], b1v = sb[ch+1];
            const int pxa = px0 + xh*8 + j;
            const int pxb = pxa + 4;
            if (pxa < P2) {
                float2 v = make_float2(fmaxf(o0 + b0v, 0.f), fmaxf(o1 + b1v, 0.f));
                *(float2*)(g_buf2 + (((size_t)b*P2 + py)*P2 + pxa)*32 + ch) = v;
            }
            if (pxb < P2) {
                float2 v = make_float2(fmaxf(o2 + b0v, 0.f), fmaxf(o3 + b1v, 0.f));
                *(float2*)(g_buf2 + (((size_t)b*P2 + py)*P2 + pxb)*32 + ch) = v;
            }
        }
    }
}

// ===========================================================================
// dense1 split-K GEMM: [128 x 119072] @ [119072 x 120] -> partials.
// grid KSPLITS(=128) blocks, 512 threads; all 120 outputs per block,
// so g_buf2 is read exactly once.  f32x2-packed inner loop.
// ===========================================================================
__global__ void __launch_bounds__(512) dense1_kernel(const float* __restrict__ w)
{
    __shared__ __align__(16) float As[32*129];
    __shared__ __align__(16) float Ws[32*120];

    const int k0   = blockIdx.x * KCHUNK;
    const int kend = min(k0 + KCHUNK, FLAT);
    const int tid  = threadIdx.x;
    const int bb   = tid & 127;
    const int g    = tid >> 7;          // 0..3 -> 30 output cols each

    ull acc[15];
#pragma unroll
    for (int j = 0; j < 15; ++j) acc[j] = 0ull;

    for (int kb = k0; kb < kend; kb += 32) {
        for (int i = tid; i < 128*32; i += 512) {
            int r  = i >> 5;
            int kk = i & 31;
            int k  = kb + kk;
            As[kk*129 + r] = (k < kend) ? g_buf2[(size_t)r*FLAT + k] : 0.f;
        }
        for (int i = tid; i < 32*120; i += 512) {
            int kk = i / 120, oo = i - kk*120;
            int k = kb + kk;
            Ws[i] = (k < kend) ? w[(size_t)k*120 + oo] : 0.f;
        }
        __syncthreads();
#pragma unroll
        for (int kk = 0; kk < 32; ++kk) {
            ull a2 = pk2(As[kk*129 + bb]);
            const ull* wsp = (const ull*)&Ws[kk*120 + g*30];
#pragma unroll
            for (int j = 0; j < 15; ++j)
                FMA2(acc[j], a2, wsp[j]);
        }
        __syncthreads();
    }

    float* p = g_part + ((size_t)blockIdx.x*BATCH + bb)*120 + g*30;
#pragma unroll
    for (int j = 0; j < 15; ++j) {
        float lo, hi;
        upk2(acc[j], lo, hi);
        p[2*j]   = lo;
        p[2*j+1] = hi;
    }
}

// ===========================================================================
// dense23: reduce split-K partials (4-way ILP) + bias + relu -> h1;
//          h2 = relu(h1 @ d2_w + b2);  theta = h2 @ d3_w + b3.
// ===========================================================================
__global__ void __launch_bounds__(128) dense23_kernel(
    const float* __restrict__ d1b,
    const float* __restrict__ d2w, const float* __restrict__ d2b,
    const float* __restrict__ d3w, const float* __restrict__ d3b)
{
    __shared__ float h1[120];
    __shared__ float h2[84];
    const int b = blockIdx.x, t = threadIdx.x;

    if (t < 120) {
        const float* gp = g_part + (size_t)b*120 + t;
        float s0 = d1b[t], s1 = 0.f, s2 = 0.f, s3 = 0.f;
#pragma unroll 4
        for (int i = 0; i < KSPLITS; i += 4) {
            s0 += gp[(size_t)(i+0)*BATCH*120];
            s1 += gp[(size_t)(i+1)*BATCH*120];
            s2 += gp[(size_t)(i+2)*BATCH*120];
            s3 += gp[(size_t)(i+3)*BATCH*120];
        }
        h1[t] = fmaxf((s0 + s1) + (s2 + s3), 0.f);
    }
    __syncthreads();
    if (t < 84) {
        float s = d2b[t];
#pragma unroll 4
        for (int k = 0; k < 120; ++k)
            s = fmaf(h1[k], d2w[k*84 + t], s);
        h2[t] = fmaxf(s, 0.f);
    }
    __syncthreads();
    if (t < 6) {
        float s = d3b[t];
#pragma unroll 4
        for (int k = 0; k < 84; ++k)
            s = fmaf(h2[k], d3w[k*6 + t], s);
        g_theta[b*6 + t] = s;
    }
}

// ===========================================================================
// sampler: affine grid + bilinear sample + 1x1 conv + sigmoid.
// ===========================================================================
__global__ void __launch_bounds__(256) sampler_kernel(
    const float* __restrict__ x, const float* __restrict__ ow,
    const float* __restrict__ ob, float* __restrict__ out)
{
    __shared__ float th[6];
    const int b = blockIdx.y;
    const int h = blockIdx.x;
    const int w = threadIdx.x;
    if (w < 6) th[w] = g_theta[b*6 + w];
    __syncthreads();

    const float gx = (float)w * (2.f/256.f) - 1.f;
    const float gy = (float)h * (2.f/256.f) - 1.f;
    const float px = (th[0]*gx + th[1]*gy + th[2] + 1.f) * 128.f;
    const float py = (th[3]*gx + th[4]*gy + th[5] + 1.f) * 128.f;

    const int fx = (int)floorf(px);
    const int fy = (int)floorf(py);
    const int x1 = min(max(fx,     0), HW-1);
    const int x2 = min(max(fx + 1, 0), HW-1);
    const int y1 = min(max(fy,     0), HW-1);
    const int y2 = min(max(fy + 1, 0), HW-1);

    const float* img = x + (size_t)b * (HW*HW);
    const float p11 = img[y1*HW + x1];
    const float p12 = img[y2*HW + x1];
    const float p21 = img[y1*HW + x2];
    const float p22 = img[y2*HW + x2];

    const float wx1 = (float)x2 - px;
    const float wx2 = px - (float)x1;
    const float wy1 = (float)y2 - py;
    const float wy2 = py - (float)y1;

    const float r = wx1*(wy1*p11 + wy2*p12) + wx2*(wy1*p21 + wy2*p22);
    const float t = r * __ldg(ow) + __ldg(ob);
    out[((size_t)b*HW + h)*HW + w] = 1.f / (1.f + expf(-t));
}

// ===========================================================================
// launch
// ===========================================================================
extern "C" void kernel_launch(void* const* d_in, const int* in_sizes, int n_in,
                              void* d_out, int out_size)
{
    const float* x      = (const float*)d_in[0];
    const float* c1w    = (const float*)d_in[1];
    const float* c1b    = (const float*)d_in[2];
    const float* c2w    = (const float*)d_in[3];
    const float* c2b    = (const float*)d_in[4];
    const float* d1w    = (const float*)d_in[5];
    const float* d1b    = (const float*)d_in[6];
    const float* d2w    = (const float*)d_in[7];
    const float* d2b    = (const float*)d_in[8];
    const float* d3w    = (const float*)d_in[9];
    const float* d3b    = (const float*)d_in[10];
    const float* outw   = (const float*)d_in[11];
    const float* outb   = (const float*)d_in[12];
    float* out = (float*)d_out;

    (void)in_sizes; (void)n_in; (void)out_size;

    cudaFuncSetAttribute(conv2_kernel,
                         cudaFuncAttributeMaxDynamicSharedMemorySize, C2_SMEM_B);

    conv1_kernel<<<dim3(8, 8, BATCH), 256>>>(x, c1w, c1b);
    conv2_kernel<<<dim3(4, 4, BATCH), 512, C2_SMEM_B>>>(c2w, c2b);
    dense1_kernel<<<KSPLITS, 512>>>(d1w);
    dense23_kernel<<<BATCH, 128>>>(d1b, d2w, d2b, d3w, d3b);
    sampler_kernel<<<dim3(HW, BATCH), 256>>>(x, outw, outb, out);
}

// round 8
// speedup vs baseline: 1.4632x; 1.1131x over previous
#include <cuda_runtime.h>
#include <cuda_fp16.h>
#include <math.h>

// ---------------------------------------------------------------------------
// SpatialTransformerInputHead  (B=128, H=W=256, C=1)
//   conv1 5x5 1->14 + relu + maxpool2  (fp32 f32x2)         -> g_buf1 fp32 NHWC16
//   conv2 5x5 14->32 + relu + maxpool2 (fp16 HMMA, fp32 acc)-> g_buf2 fp32 NHWC
//   dense 119072->120 relu, 120->84 relu, 84->6 -> theta
//   bilinear grid sample + 1x1 conv + sigmoid -> [128,256,256,1]
// ---------------------------------------------------------------------------

typedef unsigned long long ull;
typedef unsigned int uint32;

#define BATCH 128
#define HW    256
#define P1    126
#define P2    61
#define FLAT  (61*61*32)   // 119072
#define KSPLITS 128
#define KCHUNK  931        // ceil(119072/128)

// --------- scratch -----------------------------------------------------------
__device__ float g_buf1[(size_t)BATCH*P1*P1*16];   // conv1 pooled, NHWC16, fp32
__device__ float g_buf2[(size_t)BATCH*FLAT];       // conv2 pooled, NHWC flat, fp32
__device__ float g_part[(size_t)KSPLITS*BATCH*120];
__device__ float g_theta[BATCH*6];

// --------- helpers -----------------------------------------------------------
__device__ __forceinline__ ull pk2(float v) {
    ull r;
    asm("mov.b64 %0, {%1, %2};" : "=l"(r) : "f"(v), "f"(v));
    return r;
}
__device__ __forceinline__ void upk2(ull v, float& lo, float& hi) {
    asm("mov.b64 {%0, %1}, %2;" : "=f"(lo), "=f"(hi) : "l"(v));
}
#define FMA2(d, a, b) asm("fma.rn.f32x2 %0, %1, %2, %0;" : "+l"(d) : "l"(a), "l"(b))

__device__ __forceinline__ uint32 smem_u32(const void* p) {
    uint32 a;
    asm("{ .reg .u64 t; cvta.to.shared.u64 t, %1; cvt.u32.u64 %0, t; }"
        : "=r"(a) : "l"(p));
    return a;
}

#define MMA_F16(c, a0, a1, a2, a3, b0, b1)                                     \
    asm volatile(                                                              \
        "mma.sync.aligned.m16n8k16.row.col.f32.f16.f16.f32 "                   \
        "{%0,%1,%2,%3}, {%4,%5,%6,%7}, {%8,%9}, {%0,%1,%2,%3};"                \
        : "+f"((c)[0]), "+f"((c)[1]), "+f"((c)[2]), "+f"((c)[3])               \
        : "r"(a0), "r"(a1), "r"(a2), "r"(a3), "r"(b0), "r"(b1))

#define LDSM_X4(r0, r1, r2, r3, addr)                                          \
    asm volatile("ldmatrix.sync.aligned.m8n8.x4.shared.b16 {%0,%1,%2,%3}, [%4];" \
        : "=r"(r0), "=r"(r1), "=r"(r2), "=r"(r3) : "r"(addr))

// ===========================================================================
// conv1 (5x5, 1->14) + relu + maxpool2, fp32 f32x2 math, fp32 NHWC16 output.
// grid (8,8,128), 256 threads.
// ===========================================================================
__global__ void __launch_bounds__(256) conv1_kernel(
    const float* __restrict__ x, const float* __restrict__ w,
    const float* __restrict__ bias)
{
    __shared__ __align__(16) float sw[352];
    __shared__ __align__(16) float sb[16];
    __shared__ __align__(16) float sin_[36*36];

    const int b  = blockIdx.z;
    const int ox = blockIdx.x * 32;
    const int oy = blockIdx.y * 32;
    const int tid = threadIdx.x;

    for (int i = tid; i < 350; i += 256) sw[i] = w[i];
    if (tid < 14)  sb[tid] = bias[tid];

    const float* xb = x + (size_t)b * (HW*HW);
    for (int i = tid; i < 36*36; i += 256) {
        int r = i / 36, c = i % 36;
        int gy = oy + r, gx = ox + c;
        sin_[i] = (gy < HW && gx < HW) ? xb[gy*HW + gx] : 0.f;
    }
    __syncthreads();

    const int tx = tid & 15, ty = tid >> 4;

    ull acc[4][7];
#pragma unroll
    for (int p = 0; p < 4; ++p)
#pragma unroll
        for (int j = 0; j < 7; ++j) acc[p][j] = 0ull;

    const float* ib = sin_ + (2*ty)*36 + 2*tx;
#pragma unroll
    for (int dy = 0; dy < 5; ++dy) {
        const float* ra = ib + dy*36;
        const float* rb = ra + 36;
#pragma unroll
        for (int dx = 0; dx < 5; ++dx) {
            ull p00 = pk2(ra[dx]);
            ull p01 = pk2(ra[dx+1]);
            ull p10 = pk2(rb[dx]);
            ull p11 = pk2(rb[dx+1]);
            const ull* wp = (const ull*)&sw[(dy*5 + dx)*14];
#pragma unroll
            for (int j = 0; j < 7; ++j) {
                ull wv = wp[j];
                FMA2(acc[0][j], p00, wv);
                FMA2(acc[1][j], p01, wv);
                FMA2(acc[2][j], p10, wv);
                FMA2(acc[3][j], p11, wv);
            }
        }
    }

    const int x0 = blockIdx.x*16 + tx;
    const int y0 = blockIdx.y*16 + ty;
    if (x0 < P1 && y0 < P1) {
        union { float4 f4[4]; float f[16]; } pk;
#pragma unroll
        for (int j = 0; j < 7; ++j) {
            float l0,h0,l1,h1,l2,h2,l3,h3;
            upk2(acc[0][j], l0, h0);
            upk2(acc[1][j], l1, h1);
            upk2(acc[2][j], l2, h2);
            upk2(acc[3][j], l3, h3);
            float m0 = fmaxf(fmaxf(l0,l1), fmaxf(l2,l3)) + sb[2*j];
            float m1 = fmaxf(fmaxf(h0,h1), fmaxf(h2,h3)) + sb[2*j+1];
            pk.f[2*j]   = fmaxf(m0, 0.f);
            pk.f[2*j+1] = fmaxf(m1, 0.f);
        }
        pk.f[14] = 0.f;
        pk.f[15] = 0.f;
        float4* dst = (float4*)(g_buf1 + ((size_t)(b*P1 + y0)*P1 + x0)*16);
        dst[0] = pk.f4[0]; dst[1] = pk.f4[1];
        dst[2] = pk.f4[2]; dst[3] = pk.f4[3];
    }
}

// ===========================================================================
// conv2 via fp16 mma.sync m16n8k16 (fp32 accum): 5x5 conv = 25 shifted GEMMs,
// K = 16 padded channels per tap.  Block: 16x16 pooled = 32x32 conv positions,
// 512 threads (16 warps), each warp: 2 conv rows x 32 cols (M=64) x N=32.
// A: [36*36 pos][24 pad fp16] (48B rows -> conflict-free LDSM).
// W: [25 tap][32 co][24 pad fp16] (48B rows -> conflict-free LDS).
// Epilogue: 2x2 maxpool + bias + relu -> fp32 NHWC flat g_buf2.
// ===========================================================================
#define C2_A_B    (1296*48)                 // 62208 B
#define C2_W_B    (25*32*48)                // 38400 B
#define C2_BIAS_B 128
#define C2_SMEM_B (C2_A_B + C2_W_B + C2_BIAS_B)   // 100736 B

__global__ void __launch_bounds__(512) conv2_kernel(
    const float* __restrict__ w, const float* __restrict__ bias)
{
    extern __shared__ __align__(16) unsigned char smem[];
    __half* At = (__half*)smem;                        // [pos][24]
    __half* Wt = (__half*)(smem + C2_A_B);             // [tap][co32][24]
    float*  sb = (float*)(smem + C2_A_B + C2_W_B);     // [32]

    const int b   = blockIdx.z;
    const int px0 = blockIdx.x * 16;
    const int py0 = blockIdx.y * 16;
    const int ix0 = px0 * 2;
    const int iy0 = py0 * 2;
    const int tid = threadIdx.x;

    // weights: HWIO fp32 [tap][ci(14)][co(32)] -> fp16 Wt[tap][co][ci pad24]
    for (int i = tid; i < 25*32*24; i += 512) {
        int tap = i / 768;
        int rem = i - tap*768;
        int n   = rem / 24;          // co
        int k   = rem - n*24;        // ci
        float v = (k < 14) ? w[tap*448 + k*32 + n] : 0.f;
        Wt[i] = __float2half_rn(v);
    }
    if (tid < 32) sb[tid] = bias[tid];

    // A tile: 36x36 positions x 16 ch fp32 -> fp16, pad to 24 (48B rows)
    for (int p = tid; p < 1296; p += 512) {
        int r = p / 36, c = p % 36;
        int gy = iy0 + r, gx = ix0 + c;
        uint4 u0 = make_uint4(0,0,0,0), u1 = u0, u2 = u0;
        if (gy < P1 && gx < P1) {
            const float4* s4 = (const float4*)(g_buf1 + ((size_t)(b*P1 + gy)*P1 + gx)*16);
            float4 v0 = s4[0], v1 = s4[1], v2 = s4[2], v3 = s4[3];
            __half2 h0 = __float22half2_rn(make_float2(v0.x, v0.y));
            __half2 h1 = __float22half2_rn(make_float2(v0.z, v0.w));
            __half2 h2 = __float22half2_rn(make_float2(v1.x, v1.y));
            __half2 h3 = __float22half2_rn(make_float2(v1.z, v1.w));
            __half2 h4 = __float22half2_rn(make_float2(v2.x, v2.y));
            __half2 h5 = __float22half2_rn(make_float2(v2.z, v2.w));
            __half2 h6 = __float22half2_rn(make_float2(v3.x, v3.y));
            __half2 h7 = __float22half2_rn(make_float2(0.f, 0.f));
            u0 = make_uint4(*(uint32*)&h0, *(uint32*)&h1, *(uint32*)&h2, *(uint32*)&h3);
            u1 = make_uint4(*(uint32*)&h4, *(uint32*)&h5, *(uint32*)&h6, *(uint32*)&h7);
        }
        uint4* d = (uint4*)(At + p*24);
        d[0] = u0; d[1] = u1; d[2] = u2;
    }
    __syncthreads();

    const int warp = tid >> 5, lane = tid & 31;
    const int y0 = 2 * warp;           // conv rows y0, y0+1
    const uint32 atb = smem_u32(At);

    // per-lane LDSM offset: rows = x positions (48B stride), 16B k-halves
    const uint32 aoff = (uint32)((lane & 15)*48 + (lane >> 4)*16);
    const int nlocal = lane >> 2, k2 = (lane & 3) * 2;

    float cacc[2][2][4][4];
#pragma unroll
    for (int s = 0; s < 2; ++s)
#pragma unroll
        for (int xh = 0; xh < 2; ++xh)
#pragma unroll
            for (int nf = 0; nf < 4; ++nf)
#pragma unroll
                for (int k = 0; k < 4; ++k) cacc[s][xh][nf][k] = 0.f;

#pragma unroll 1
    for (int tap = 0; tap < 25; ++tap) {
        const int dy = tap / 5, dx = tap - 5*dy;

        // B fragments (col-major K x N): b0={k2,k2+1 @ n}, b1={k2+8,k2+9 @ n}
        uint32 bf[4][2];
        const __half* wt = Wt + tap*768;
#pragma unroll
        for (int nf = 0; nf < 4; ++nf) {
            const __half* wn = wt + (nf*8 + nlocal)*24 + k2;
            bf[nf][0] = *(const uint32*)(wn);
            bf[nf][1] = *(const uint32*)(wn + 8);
        }

#pragma unroll
        for (int s = 0; s < 2; ++s) {
            const int rowbase = (y0 + s + dy)*36 + dx;
#pragma unroll
            for (int xh = 0; xh < 2; ++xh) {
                uint32 a0, a1, a2, a3;
                LDSM_X4(a0, a1, a2, a3,
                        atb + (uint32)((rowbase + xh*16)*48) + aoff);
#pragma unroll
                for (int nf = 0; nf < 4; ++nf)
                    MMA_F16(cacc[s][xh][nf], a0, a1, a2, a3, bf[nf][0], bf[nf][1]);
            }
        }
    }

    // epilogue: 2x2 maxpool (y across s, x across frag-row pairs) + bias + relu
    const int py = py0 + warp;
    const int r  = lane >> 2;
    const bool active = ((r & 1) == 0);
    const int j = r >> 1;
    const int n0 = (lane & 3) * 2;

#pragma unroll
    for (int xh = 0; xh < 2; ++xh)
#pragma unroll
    for (int nf = 0; nf < 4; ++nf) {
        float m0 = fmaxf(cacc[0][xh][nf][0], cacc[1][xh][nf][0]);
        float m1 = fmaxf(cacc[0][xh][nf][1], cacc[1][xh][nf][1]);
        float m2 = fmaxf(cacc[0][xh][nf][2], cacc[1][xh][nf][2]);
        float m3 = fmaxf(cacc[0][xh][nf][3], cacc[1][xh][nf][3]);
        float o0 = fmaxf(m0, __shfl_down_sync(0xffffffffu, m0, 4));
        float o1 = fmaxf(m1, __shfl_down_sync(0xffffffffu, m1, 4));
        float o2 = fmaxf(m2, __shfl_down_sync(0xffffffffu, m2, 4));
        float o3 = fmaxf(m3, __shfl_down_sync(0xffffffffu, m3, 4));
        if (active && py < P2) {
            const int ch  = nf*8 + n0;
            const float b0v = sb[ch], b1v = sb[ch+1];
            const int pxa = px0 + xh*8 + j;
            const int pxb = pxa + 4;
            if (pxa < P2) {
                float2 v = make_float2(fmaxf(o0 + b0v, 0.f), fmaxf(o1 + b1v, 0.f));
                *(float2*)(g_buf2 + (((size_t)b*P2 + py)*P2 + pxa)*32 + ch) = v;
            }
            if (pxb < P2) {
                float2 v = make_float2(fmaxf(o2 + b0v, 0.f), fmaxf(o3 + b1v, 0.f));
                *(float2*)(g_buf2 + (((size_t)b*P2 + py)*P2 + pxb)*32 + ch) = v;
            }
        }
    }
}

// ===========================================================================
// dense1 split-K GEMM: [128 x 119072] @ [119072 x 120] -> partials.
// grid KSPLITS(=128) blocks, 512 threads; f32x2-packed inner loop.
// ===========================================================================
__global__ void __launch_bounds__(512) dense1_kernel(const float* __restrict__ w)
{
    __shared__ __align__(16) float As[32*129];
    __shared__ __align__(16) float Ws[32*120];

    const int k0   = blockIdx.x * KCHUNK;
    const int kend = min(k0 + KCHUNK, FLAT);
    const int tid  = threadIdx.x;
    const int bb   = tid & 127;
    const int g    = tid >> 7;          // 0..3 -> 30 output cols each

    ull acc[15];
#pragma unroll
    for (int j = 0; j < 15; ++j) acc[j] = 0ull;

    for (int kb = k0; kb < kend; kb += 32) {
        for (int i = tid; i < 128*32; i += 512) {
            int r  = i >> 5;
            int kk = i & 31;
            int k  = kb + kk;
            As[kk*129 + r] = (k < kend) ? g_buf2[(size_t)r*FLAT + k] : 0.f;
        }
        for (int i = tid; i < 32*120; i += 512) {
            int kk = i / 120, oo = i - kk*120;
            int k = kb + kk;
            Ws[i] = (k < kend) ? w[(size_t)k*120 + oo] : 0.f;
        }
        __syncthreads();
#pragma unroll
        for (int kk = 0; kk < 32; ++kk) {
            ull a2 = pk2(As[kk*129 + bb]);
            const ull* wsp = (const ull*)&Ws[kk*120 + g*30];
#pragma unroll
            for (int j = 0; j < 15; ++j)
                FMA2(acc[j], a2, wsp[j]);
        }
        __syncthreads();
    }

    float* p = g_part + ((size_t)blockIdx.x*BATCH + bb)*120 + g*30;
#pragma unroll
    for (int j = 0; j < 15; ++j) {
        float lo, hi;
        upk2(acc[j], lo, hi);
        p[2*j]   = lo;
        p[2*j+1] = hi;
    }
}

// ===========================================================================
// dense23: reduce split-K partials (4-way ILP) + bias + relu -> h1;
//          h2 = relu(h1 @ d2_w + b2);  theta = h2 @ d3_w + b3.
// ===========================================================================
__global__ void __launch_bounds__(128) dense23_kernel(
    const float* __restrict__ d1b,
    const float* __restrict__ d2w, const float* __restrict__ d2b,
    const float* __restrict__ d3w, const float* __restrict__ d3b)
{
    __shared__ float h1[120];
    __shared__ float h2[84];
    const int b = blockIdx.x, t = threadIdx.x;

    if (t < 120) {
        const float* gp = g_part + (size_t)b*120 + t;
        float s0 = d1b[t], s1 = 0.f, s2 = 0.f, s3 = 0.f;
#pragma unroll 4
        for (int i = 0; i < KSPLITS; i += 4) {
            s0 += gp[(size_t)(i+0)*BATCH*120];
            s1 += gp[(size_t)(i+1)*BATCH*120];
            s2 += gp[(size_t)(i+2)*BATCH*120];
            s3 += gp[(size_t)(i+3)*BATCH*120];
        }
        h1[t] = fmaxf((s0 + s1) + (s2 + s3), 0.f);
    }
    __syncthreads();
    if (t < 84) {
        float s = d2b[t];
#pragma unroll 4
        for (int k = 0; k < 120; ++k)
            s = fmaf(h1[k], d2w[k*84 + t], s);
        h2[t] = fmaxf(s, 0.f);
    }
    __syncthreads();
    if (t < 6) {
        float s = d3b[t];
#pragma unroll 4
        for (int k = 0; k < 84; ++k)
            s = fmaf(h2[k], d3w[k*6 + t], s);
        g_theta[b*6 + t] = s;
    }
}

// ===========================================================================
// sampler: affine grid + bilinear sample + 1x1 conv + sigmoid.
// ===========================================================================
__global__ void __launch_bounds__(256) sampler_kernel(
    const float* __restrict__ x, const float* __restrict__ ow,
    const float* __restrict__ ob, float* __restrict__ out)
{
    __shared__ float th[6];
    const int b = blockIdx.y;
    const int h = blockIdx.x;
    const int w = threadIdx.x;
    if (w < 6) th[w] = g_theta[b*6 + w];
    __syncthreads();

    const float gx = (float)w * (2.f/256.f) - 1.f;
    const float gy = (float)h * (2.f/256.f) - 1.f;
    const float px = (th[0]*gx + th[1]*gy + th[2] + 1.f) * 128.f;
    const float py = (th[3]*gx + th[4]*gy + th[5] + 1.f) * 128.f;

    const int fx = (int)floorf(px);
    const int fy = (int)floorf(py);
    const int x1 = min(max(fx,     0), HW-1);
    const int x2 = min(max(fx + 1, 0), HW-1);
    const int y1 = min(max(fy,     0), HW-1);
    const int y2 = min(max(fy + 1, 0), HW-1);

    const float* img = x + (size_t)b * (HW*HW);
    const float p11 = img[y1*HW + x1];
    const float p12 = img[y2*HW + x1];
    const float p21 = img[y1*HW + x2];
    const float p22 = img[y2*HW + x2];

    const float wx1 = (float)x2 - px;
    const float wx2 = px - (float)x1;
    const float wy1 = (float)y2 - py;
    const float wy2 = py - (float)y1;

    const float r = wx1*(wy1*p11 + wy2*p12) + wx2*(wy1*p21 + wy2*p22);
    const float t = r * __ldg(ow) + __ldg(ob);
    out[((size_t)b*HW + h)*HW + w] = 1.f / (1.f + expf(-t));
}

// ===========================================================================
// launch
// ===========================================================================
extern "C" void kernel_launch(void* const* d_in, const int* in_sizes, int n_in,
                              void* d_out, int out_size)
{
    const float* x      = (const float*)d_in[0];
    const float* c1w    = (const float*)d_in[1];
    const float* c1b    = (const float*)d_in[2];
    const float* c2w    = (const float*)d_in[3];
    const float* c2b    = (const float*)d_in[4];
    const float* d1w    = (const float*)d_in[5];
    const float* d1b    = (const float*)d_in[6];
    const float* d2w    = (const float*)d_in[7];
    const float* d2b    = (const float*)d_in[8];
    const float* d3w    = (const float*)d_in[9];
    const float* d3b    = (const float*)d_in[10];
    const float* outw   = (const float*)d_in[11];
    const float* outb   = (const float*)d_in[12];
    float* out = (float*)d_out;

    (void)in_sizes; (void)n_in; (void)out_size;

    cudaFuncSetAttribute(conv2_kernel,
                         cudaFuncAttributeMaxDynamicSharedMemorySize, C2_SMEM_B);

    conv1_kernel<<<dim3(8, 8, BATCH), 256>>>(x, c1w, c1b);
    conv2_kernel<<<dim3(4, 4, BATCH), 512, C2_SMEM_B>>>(c2w, c2b);
    dense1_kernel<<<KSPLITS, 512>>>(d1w);
    dense23_kernel<<<BATCH, 128>>>(d1b, d2w, d2b, d3w, d3b);
    sampler_kernel<<<dim3(HW, BATCH), 256>>>(x, outw, outb, out);
}

// round 9
// speedup vs baseline: 2.0230x; 1.3826x over previous
#include <cuda_runtime.h>
#include <cuda_fp16.h>
#include <math.h>

// ---------------------------------------------------------------------------
// SpatialTransformerInputHead  (B=128, H=W=256, C=1)
//   conv1 5x5 1->14 + relu + maxpool2  (fp32 f32x2)         -> g_buf1 fp16 NHWC16
//   conv2 5x5 14->32 + relu + maxpool2 (fp16 HMMA, fp32 acc)-> g_buf2 fp32 NHWC
//   dense 119072->120 relu, 120->84 relu, 84->6 -> theta
//   bilinear grid sample + 1x1 conv + sigmoid -> [128,256,256,1]
// ---------------------------------------------------------------------------

typedef unsigned long long ull;
typedef unsigned int uint32;

#define BATCH 128
#define HW    256
#define P1    126
#define P2    61
#define FLAT  (61*61*32)   // 119072
#define KSPLITS 256
#define KCHUNK  466        // ceil(119072/256)

// --------- scratch -----------------------------------------------------------
__device__ __half g_buf1[(size_t)BATCH*P1*P1*16];  // conv1 pooled, NHWC16, fp16
__device__ __half g_w16[25*32*24];                 // conv2 weights fp16 [tap][co][k24]
__device__ float  g_buf2[(size_t)BATCH*FLAT];      // conv2 pooled, NHWC flat, fp32
__device__ float  g_part[(size_t)KSPLITS*BATCH*120];
__device__ float  g_theta[BATCH*6];

// --------- helpers -----------------------------------------------------------
__device__ __forceinline__ ull pk2(float v) {
    ull r;
    asm("mov.b64 %0, {%1, %2};" : "=l"(r) : "f"(v), "f"(v));
    return r;
}
__device__ __forceinline__ void upk2(ull v, float& lo, float& hi) {
    asm("mov.b64 {%0, %1}, %2;" : "=f"(lo), "=f"(hi) : "l"(v));
}
#define FMA2(d, a, b) asm("fma.rn.f32x2 %0, %1, %2, %0;" : "+l"(d) : "l"(a), "l"(b))

__device__ __forceinline__ uint32 smem_u32(const void* p) {
    uint32 a;
    asm("{ .reg .u64 t; cvta.to.shared.u64 t, %1; cvt.u32.u64 %0, t; }"
        : "=r"(a) : "l"(p));
    return a;
}

#define MMA_F16(c, a0, a1, a2, a3, b0, b1)                                     \
    asm volatile(                                                              \
        "mma.sync.aligned.m16n8k16.row.col.f32.f16.f16.f32 "                   \
        "{%0,%1,%2,%3}, {%4,%5,%6,%7}, {%8,%9}, {%0,%1,%2,%3};"                \
        : "+f"((c)[0]), "+f"((c)[1]), "+f"((c)[2]), "+f"((c)[3])               \
        : "r"(a0), "r"(a1), "r"(a2), "r"(a3), "r"(b0), "r"(b1))

#define LDSM_X4(r0, r1, r2, r3, addr)                                          \
    asm volatile("ldmatrix.sync.aligned.m8n8.x4.shared.b16 {%0,%1,%2,%3}, [%4];" \
        : "=r"(r0), "=r"(r1), "=r"(r2), "=r"(r3) : "r"(addr))

// ===========================================================================
// wprep: conv2 weights HWIO fp32 -> fp16 [tap][co(32)][ci pad 24], once.
// grid 25 (one tap per block), 256 threads.
// ===========================================================================
__global__ void __launch_bounds__(256) wprep_kernel(const float* __restrict__ w)
{
    const int tap = blockIdx.x;
    for (int i = threadIdx.x; i < 768; i += 256) {
        int n = i / 24, k = i - n*24;
        float v = (k < 14) ? w[tap*448 + k*32 + n] : 0.f;
        g_w16[tap*768 + i] = __float2half_rn(v);
    }
}

// ===========================================================================
// conv1 (5x5, 1->14) + relu + maxpool2, fp32 f32x2 math, fp16 NHWC16 output.
// grid (8,8,128), 256 threads.
// ===========================================================================
__global__ void __launch_bounds__(256) conv1_kernel(
    const float* __restrict__ x, const float* __restrict__ w,
    const float* __restrict__ bias)
{
    __shared__ __align__(16) float sw[352];
    __shared__ __align__(16) float sb[16];
    __shared__ __align__(16) float sin_[36*36];

    const int b  = blockIdx.z;
    const int ox = blockIdx.x * 32;
    const int oy = blockIdx.y * 32;
    const int tid = threadIdx.x;

    for (int i = tid; i < 350; i += 256) sw[i] = w[i];
    if (tid < 14)  sb[tid] = bias[tid];

    const float* xb = x + (size_t)b * (HW*HW);
    for (int i = tid; i < 36*36; i += 256) {
        int r = i / 36, c = i % 36;
        int gy = oy + r, gx = ox + c;
        sin_[i] = (gy < HW && gx < HW) ? xb[gy*HW + gx] : 0.f;
    }
    __syncthreads();

    const int tx = tid & 15, ty = tid >> 4;

    ull acc[4][7];
#pragma unroll
    for (int p = 0; p < 4; ++p)
#pragma unroll
        for (int j = 0; j < 7; ++j) acc[p][j] = 0ull;

    const float* ib = sin_ + (2*ty)*36 + 2*tx;
#pragma unroll
    for (int dy = 0; dy < 5; ++dy) {
        const float* ra = ib + dy*36;
        const float* rb = ra + 36;
#pragma unroll
        for (int dx = 0; dx < 5; ++dx) {
            ull p00 = pk2(ra[dx]);
            ull p01 = pk2(ra[dx+1]);
            ull p10 = pk2(rb[dx]);
            ull p11 = pk2(rb[dx+1]);
            const ull* wp = (const ull*)&sw[(dy*5 + dx)*14];
#pragma unroll
            for (int j = 0; j < 7; ++j) {
                ull wv = wp[j];
                FMA2(acc[0][j], p00, wv);
                FMA2(acc[1][j], p01, wv);
                FMA2(acc[2][j], p10, wv);
                FMA2(acc[3][j], p11, wv);
            }
        }
    }

    const int x0 = blockIdx.x*16 + tx;
    const int y0 = blockIdx.y*16 + ty;
    if (x0 < P1 && y0 < P1) {
        union { uint4 u[2]; __half2 h2[8]; } pk;
#pragma unroll
        for (int j = 0; j < 7; ++j) {
            float l0,h0,l1,h1,l2,h2,l3,h3;
            upk2(acc[0][j], l0, h0);
            upk2(acc[1][j], l1, h1);
            upk2(acc[2][j], l2, h2);
            upk2(acc[3][j], l3, h3);
            float m0 = fmaxf(fmaxf(l0,l1), fmaxf(l2,l3)) + sb[2*j];
            float m1 = fmaxf(fmaxf(h0,h1), fmaxf(h2,h3)) + sb[2*j+1];
            pk.h2[j] = __float22half2_rn(make_float2(fmaxf(m0, 0.f), fmaxf(m1, 0.f)));
        }
        pk.h2[7] = __float22half2_rn(make_float2(0.f, 0.f));
        uint4* dst = (uint4*)(g_buf1 + ((size_t)(b*P1 + y0)*P1 + x0)*16);
        dst[0] = pk.u[0];
        dst[1] = pk.u[1];
    }
}

// ===========================================================================
// conv2 via fp16 mma.sync m16n8k16 (fp32 accum): 5x5 conv = 25 shifted GEMMs.
// Block: 8x16 pooled = 16x32 conv positions, 256 threads (8 warps),
// each warp 2 conv rows x 32 cols (M=64) x N=32.  2 blocks/SM.
// A: [20*36 pos][24 pad fp16] (48B rows, conflict-free LDSM).
// W: fp16 [25 tap][32 co][24 k] copied from g_w16; B-frags via ldmatrix.
// Epilogue: 2x2 maxpool + bias + relu -> fp32 NHWC flat g_buf2.
// ===========================================================================
#define C2_A_B    (720*48)                  // 34560 B (20 rows x 36 cols)
#define C2_W_B    (25*32*48)                // 38400 B
#define C2_SMEM_B (C2_A_B + C2_W_B + 128)   // 73088 B

__global__ void __launch_bounds__(256, 2) conv2_kernel(const float* __restrict__ bias)
{
    extern __shared__ __align__(16) unsigned char smem[];
    __half* At = (__half*)smem;                        // [pos 20x36][24]
    __half* Wt = (__half*)(smem + C2_A_B);             // [tap][co32][24]
    float*  sb = (float*)(smem + C2_A_B + C2_W_B);     // [32]

    const int b   = blockIdx.z;
    const int px0 = blockIdx.x * 16;
    const int py0 = blockIdx.y * 8;
    const int ix0 = px0 * 2;
    const int iy0 = py0 * 2;
    const int tid = threadIdx.x;

    // W: straight 38.4KB vector copy from preconverted fp16
    {
        const uint4* ws = (const uint4*)g_w16;
        uint4* wd = (uint4*)Wt;
        for (int i = tid; i < C2_W_B/16; i += 256) wd[i] = ws[i];
    }
    if (tid < 32) sb[tid] = bias[tid];

    // A tile: 20x36 positions, 32B fp16 copy + 16B zero pad (48B rows)
    for (int p = tid; p < 720; p += 256) {
        int r = p / 36, c = p - r*36;
        int gy = iy0 + r, gx = ix0 + c;
        uint4 u0 = make_uint4(0,0,0,0), u1 = u0;
        if (gy < P1 && gx < P1) {
            const uint4* s4 = (const uint4*)(g_buf1 + ((size_t)(b*P1 + gy)*P1 + gx)*16);
            u0 = s4[0]; u1 = s4[1];
        }
        uint4* d = (uint4*)(At + p*24);
        d[0] = u0; d[1] = u1; d[2] = make_uint4(0,0,0,0);
    }
    __syncthreads();

    const int warp = tid >> 5, lane = tid & 31;
    const int y0 = 2 * warp;                 // conv rows y0, y0+1 (0..15)
    const uint32 atb = smem_u32(At);
    const uint32 wtb = smem_u32(Wt);

    // A-LDSM per-lane offset: 16 x-position rows (48B stride), 16B k-halves
    const uint32 aoff = (uint32)((lane & 15)*48 + (lane >> 4)*16);
    // B-LDSM per-lane offset: mat0..3 = (n0-7,k0-7),(n0-7,k8-15),(n8-15,k0-7),(n8-15,k8-15)
    const uint32 boff = (uint32)(((lane & 7) + ((lane >> 4) & 1)*8)*48
                                 + ((lane >> 3) & 1)*16);

    float cacc[2][2][4][4];
#pragma unroll
    for (int s = 0; s < 2; ++s)
#pragma unroll
        for (int xh = 0; xh < 2; ++xh)
#pragma unroll
            for (int nf = 0; nf < 4; ++nf)
#pragma unroll
                for (int k = 0; k < 4; ++k) cacc[s][xh][nf][k] = 0.f;

#pragma unroll 1
    for (int tap = 0; tap < 25; ++tap) {
        const int dy = tap / 5, dx = tap - 5*dy;

        // B fragments for all 4 n-frags: 2x ldmatrix.x4
        const uint32 wb = wtb + (uint32)(tap*1536) + boff;
        uint32 b00, b01, b10, b11, b20, b21, b30, b31;
        LDSM_X4(b00, b01, b10, b11, wb);            // nf0: b0,b1 ; nf1: b0,b1
        LDSM_X4(b20, b21, b30, b31, wb + 768);      // nf2, nf3 (n offset 16 rows)

#pragma unroll
        for (int s = 0; s < 2; ++s) {
            const int rowbase = (y0 + s + dy)*36 + dx;
#pragma unroll
            for (int xh = 0; xh < 2; ++xh) {
                uint32 a0, a1, a2, a3;
                LDSM_X4(a0, a1, a2, a3,
                        atb + (uint32)((rowbase + xh*16)*48) + aoff);
                MMA_F16(cacc[s][xh][0], a0, a1, a2, a3, b00, b01);
                MMA_F16(cacc[s][xh][1], a0, a1, a2, a3, b10, b11);
                MMA_F16(cacc[s][xh][2], a0, a1, a2, a3, b20, b21);
                MMA_F16(cacc[s][xh][3], a0, a1, a2, a3, b30, b31);
            }
        }
    }

    // epilogue: 2x2 maxpool (y across s, x across frag-row pairs) + bias + relu
    const int py = py0 + warp;
    const int r  = lane >> 2;
    const bool active = ((r & 1) == 0);
    const int j = r >> 1;
    const int n0 = (lane & 3) * 2;

#pragma unroll
    for (int xh = 0; xh < 2; ++xh)
#pragma unroll
    for (int nf = 0; nf < 4; ++nf) {
        float m0 = fmaxf(cacc[0][xh][nf][0], cacc[1][xh][nf][0]);
        float m1 = fmaxf(cacc[0][xh][nf][1], cacc[1][xh][nf][1]);
        float m2 = fmaxf(cacc[0][xh][nf][2], cacc[1][xh][nf][2]);
        float m3 = fmaxf(cacc[0][xh][nf][3], cacc[1][xh][nf][3]);
        float o0 = fmaxf(m0, __shfl_down_sync(0xffffffffu, m0, 4));
        float o1 = fmaxf(m1, __shfl_down_sync(0xffffffffu, m1, 4));
        float o2 = fmaxf(m2, __shfl_down_sync(0xffffffffu, m2, 4));
        float o3 = fmaxf(m3, __shfl_down_sync(0xffffffffu, m3, 4));
        if (active && py < P2) {
            const int ch  = nf*8 + n0;
            const float b0v = sb[ch], b1v = sb[ch+1];
            const int pxa = px0 + xh*8 + j;
            const int pxb = pxa + 4;
            if (pxa < P2) {
                float2 v = make_float2(fmaxf(o0 + b0v, 0.f), fmaxf(o1 + b1v, 0.f));
                *(float2*)(g_buf2 + (((size_t)b*P2 + py)*P2 + pxa)*32 + ch) = v;
            }
            if (pxb < P2) {
                float2 v = make_float2(fmaxf(o2 + b0v, 0.f), fmaxf(o3 + b1v, 0.f));
                *(float2*)(g_buf2 + (((size_t)b*P2 + py)*P2 + pxb)*32 + ch) = v;
            }
        }
    }
}

// ===========================================================================
// dense1 split-K GEMM: [128 x 119072] @ [119072 x 120] -> partials.
// grid KSPLITS(=256) blocks, 512 threads; f32x2-packed inner loop.
// ===========================================================================
__global__ void __launch_bounds__(512) dense1_kernel(const float* __restrict__ w)
{
    __shared__ __align__(16) float As[32*129];
    __shared__ __align__(16) float Ws[32*120];

    const int k0   = blockIdx.x * KCHUNK;
    const int kend = min(k0 + KCHUNK, FLAT);
    const int tid  = threadIdx.x;
    const int bb   = tid & 127;
    const int g    = tid >> 7;          // 0..3 -> 30 output cols each

    ull acc[15];
#pragma unroll
    for (int j = 0; j < 15; ++j) acc[j] = 0ull;

    for (int kb = k0; kb < kend; kb += 32) {
        for (int i = tid; i < 128*32; i += 512) {
            int r  = i >> 5;
            int kk = i & 31;
            int k  = kb + kk;
            As[kk*129 + r] = (k < kend) ? g_buf2[(size_t)r*FLAT + k] : 0.f;
        }
        for (int i = tid; i < 32*120; i += 512) {
            int kk = i / 120, oo = i - kk*120;
            int k = kb + kk;
            Ws[i] = (k < kend) ? w[(size_t)k*120 + oo] : 0.f;
        }
        __syncthreads();
#pragma unroll
        for (int kk = 0; kk < 32; ++kk) {
            ull a2 = pk2(As[kk*129 + bb]);
            const ull* wsp = (const ull*)&Ws[kk*120 + g*30];
#pragma unroll
            for (int j = 0; j < 15; ++j)
                FMA2(acc[j], a2, wsp[j]);
        }
        __syncthreads();
    }

    float* p = g_part + ((size_t)blockIdx.x*BATCH + bb)*120 + g*30;
#pragma unroll
    for (int j = 0; j < 15; ++j) {
        float lo, hi;
        upk2(acc[j], lo, hi);
        p[2*j]   = lo;
        p[2*j+1] = hi;
    }
}

// ===========================================================================
// dense23: reduce split-K partials (4-way ILP) + bias + relu -> h1;
//          h2 = relu(h1 @ d2_w + b2);  theta = h2 @ d3_w + b3.
// ===========================================================================
__global__ void __launch_bounds__(128) dense23_kernel(
    const float* __restrict__ d1b,
    const float* __restrict__ d2w, const float* __restrict__ d2b,
    const float* __restrict__ d3w, const float* __restrict__ d3b)
{
    __shared__ float h1[120];
    __shared__ float h2[84];
    const int b = blockIdx.x, t = threadIdx.x;

    if (t < 120) {
        const float* gp = g_part + (size_t)b*120 + t;
        float s0 = d1b[t], s1 = 0.f, s2 = 0.f, s3 = 0.f;
#pragma unroll 4
        for (int i = 0; i < KSPLITS; i += 4) {
            s0 += gp[(size_t)(i+0)*BATCH*120];
            s1 += gp[(size_t)(i+1)*BATCH*120];
            s2 += gp[(size_t)(i+2)*BATCH*120];
            s3 += gp[(size_t)(i+3)*BATCH*120];
        }
        h1[t] = fmaxf((s0 + s1) + (s2 + s3), 0.f);
    }
    __syncthreads();
    if (t < 84) {
        float s = d2b[t];
#pragma unroll 4
        for (int k = 0; k < 120; ++k)
            s = fmaf(h1[k], d2w[k*84 + t], s);
        h2[t] = fmaxf(s, 0.f);
    }
    __syncthreads();
    if (t < 6) {
        float s = d3b[t];
#pragma unroll 4
        for (int k = 0; k < 84; ++k)
            s = fmaf(h2[k], d3w[k*6 + t], s);
        g_theta[b*6 + t] = s;
    }
}

// ===========================================================================
// sampler: affine grid + bilinear sample + 1x1 conv + sigmoid.
// ===========================================================================
__global__ void __launch_bounds__(256) sampler_kernel(
    const float* __restrict__ x, const float* __restrict__ ow,
    const float* __restrict__ ob, float* __restrict__ out)
{
    __shared__ float th[6];
    const int b = blockIdx.y;
    const int h = blockIdx.x;
    const int w = threadIdx.x;
    if (w < 6) th[w] = g_theta[b*6 + w];
    __syncthreads();

    const float gx = (float)w * (2.f/256.f) - 1.f;
    const float gy = (float)h * (2.f/256.f) - 1.f;
    const float px = (th[0]*gx + th[1]*gy + th[2] + 1.f) * 128.f;
    const float py = (th[3]*gx + th[4]*gy + th[5] + 1.f) * 128.f;

    const int fx = (int)floorf(px);
    const int fy = (int)floorf(py);
    const int x1 = min(max(fx,     0), HW-1);
    const int x2 = min(max(fx + 1, 0), HW-1);
    const int y1 = min(max(fy,     0), HW-1);
    const int y2 = min(max(fy + 1, 0), HW-1);

    const float* img = x + (size_t)b * (HW*HW);
    const float p11 = img[y1*HW + x1];
    const float p12 = img[y2*HW + x1];
    const float p21 = img[y1*HW + x2];
    const float p22 = img[y2*HW + x2];

    const float wx1 = (float)x2 - px;
    const float wx2 = px - (float)x1;
    const float wy1 = (float)y2 - py;
    const float wy2 = py - (float)y1;

    const float r = wx1*(wy1*p11 + wy2*p12) + wx2*(wy1*p21 + wy2*p22);
    const float t = r * __ldg(ow) + __ldg(ob);
    out[((size_t)b*HW + h)*HW + w] = 1.f / (1.f + expf(-t));
}

// ===========================================================================
// launch
// ===========================================================================
extern "C" void kernel_launch(void* const* d_in, const int* in_sizes, int n_in,
                              void* d_out, int out_size)
{
    const float* x      = (const float*)d_in[0];
    const float* c1w    = (const float*)d_in[1];
    const float* c1b    = (const float*)d_in[2];
    const float* c2w    = (const float*)d_in[3];
    const float* c2b    = (const float*)d_in[4];
    const float* d1w    = (const float*)d_in[5];
    const float* d1b    = (const float*)d_in[6];
    const float* d2w    = (const float*)d_in[7];
    const float* d2b    = (const float*)d_in[8];
    const float* d3w    = (const float*)d_in[9];
    const float* d3b    = (const float*)d_in[10];
    const float* outw   = (const float*)d_in[11];
    const float* outb   = (const float*)d_in[12];
    float* out = (float*)d_out;

    (void)in_sizes; (void)n_in; (void)out_size;

    cudaFuncSetAttribute(conv2_kernel,
                         cudaFuncAttributeMaxDynamicSharedMemorySize, C2_SMEM_B);

    wprep_kernel<<<25, 256>>>(c2w);
    conv1_kernel<<<dim3(8, 8, BATCH), 256>>>(x, c1w, c1b);
    conv2_kernel<<<dim3(4, 8, BATCH), 256, C2_SMEM_B>>>(c2b);
    dense1_kernel<<<KSPLITS, 512>>>(d1w);
    dense23_kernel<<<BATCH, 128>>>(d1b, d2w, d2b, d3w, d3b);
    sampler_kernel<<<dim3(HW, BATCH), 256>>>(x, outw, outb, out);
}